// round 14
// baseline (speedup 1.0000x reference)
#include <cuda_runtime.h>
#include <cuda_fp16.h>
#include <math.h>
#include <stdint.h>

#define NLVL 3
#define BATCH 2
#define NPTSB 65536
#define NCAMS 5
#define CIN 256
#define MID 128
#define OUTC 128
#define PTSC 128
#define HH 64
#define WW 112
#define NIMG (BATCH*NCAMS)          /* 10 */
#define NPIX (HH*WW)                /* 7168 */
#define KDIM (CIN*9)                /* 2304 */
#define TOTPTS (BATCH*NPTSB)        /* 131072 */
#define KCH 64                      /* K elements per pipeline chunk */
#define NCHUNK (KDIM/KCH)           /* 36 */
#define STAGE 32768                 /* A 16KB fp16 + B 16KB fp16 */

// ---------------- scratch (static device arrays) ----------------
__device__ float  g_c2[NLVL*OUTC];                             // folded conv bias [l][o]
__device__ __half g_w[(size_t)NLVL*NCHUNK*8192];               // folded conv weights fp16 (tap-major k), pre-swizzled 16KB tiles
__device__ __half g_pw[4*4096];                                // pts_w fp16, pre-swizzled 8KB chunk tiles
__device__ __half g_imgT[(size_t)NLVL*NIMG*NPIX*CIN];          // transposed+fp16 image [l][n][pix][ci]
__device__ __half g_conv[(size_t)NLVL*NIMG*NPIX*OUTC];         // projected conv features (fp16)
__device__ __half g_yimg[(size_t)TOTPTS*OUTC];                 // img branch pre-BN (fp16)
__device__ __half g_ypts[(size_t)TOTPTS*OUTC];                 // pts branch pre-BN (fp16)
__device__ double g_stats[4*OUTC];
__device__ float  g_bn[4*OUTC];

__constant__ int c_tapoff[9] = {-WW-1, -WW, -WW+1, -1, 0, 1, WW-1, WW, WW+1};

// ---------------- PTX helpers ----------------
__device__ __forceinline__ uint32_t smem_u32(const void* p) {
    uint32_t a;
    asm("{ .reg .u64 t; cvta.to.shared.u64 t, %1; cvt.u32.u64 %0, t; }" : "=r"(a) : "l"(p));
    return a;
}
#define LDSM4(r, addr) \
    asm volatile("ldmatrix.sync.aligned.m8n8.x4.shared.b16 {%0,%1,%2,%3}, [%4];" \
        : "=r"((r)[0]), "=r"((r)[1]), "=r"((r)[2]), "=r"((r)[3]) : "r"(addr))
#define MMAH16816(c, a, b0, b1) \
    asm volatile("mma.sync.aligned.m16n8k16.row.col.f32.f16.f16.f32 " \
        "{%0,%1,%2,%3}, {%4,%5,%6,%7}, {%8,%9}, {%0,%1,%2,%3};" \
        : "+f"((c)[0]), "+f"((c)[1]), "+f"((c)[2]), "+f"((c)[3]) \
        : "r"((a)[0]), "r"((a)[1]), "r"((a)[2]), "r"((a)[3]), "r"(b0), "r"(b1))
#define CP_ASYNC16(dst, src) \
    asm volatile("cp.async.cg.shared.global [%0], [%1], 16;" :: "r"(dst), "l"(src))
#define CP_ASYNC16Z(dst, src, sz) \
    asm volatile("cp.async.cg.shared.global [%0], [%1], 16, %2;" :: "r"(dst), "l"(src), "r"(sz))
#define CP_COMMIT() asm volatile("cp.async.commit_group;")
#define CP_WAIT0()  asm volatile("cp.async.wait_group 0;" ::: "memory")

// ---------------- transpose + fp16 convert: img[l][n][ci][pix] -> g_imgT[l][n][pix][ci] ----------------
__global__ __launch_bounds__(256) void transpose_kernel(const float* __restrict__ img) {
    __shared__ float t[64][33];
    const int zi = blockIdx.z;
    const int p0 = blockIdx.x * 32, c0 = blockIdx.y * 64;
    const float* src = img + (size_t)zi * CIN * NPIX;
    const int tx = threadIdx.x & 31, ty = threadIdx.x >> 5;   // ty 0..7
    #pragma unroll
    for (int j = 0; j < 8; j++)
        t[ty*8 + j][tx] = __ldg(&src[(size_t)(c0 + ty*8 + j) * NPIX + p0 + tx]);
    __syncthreads();
    __half* dst = g_imgT + (size_t)zi * NPIX * CIN;
    const int pp = threadIdx.x >> 3;        // 0..31 pixel
    const int cc = threadIdx.x & 7;         // 8-channel group
    uint32_t pk[4];
    #pragma unroll
    for (int q = 0; q < 4; q++) {
        __half2 h = __floats2half2_rn(t[cc*8 + 2*q][pp], t[cc*8 + 2*q + 1][pp]);
        pk[q] = *(uint32_t*)&h;
    }
    *(uint4*)&dst[(size_t)(p0 + pp) * CIN + c0 + cc*8] = make_uint4(pk[0], pk[1], pk[2], pk[3]);
}

// ---------------- fold as tiled GEMM: W2[l][o][k] = sum_m img_w[o][l*128+m] * conv_w[l][m][k] ----------------
__global__ __launch_bounds__(256) void fold_gemm_kernel(const float* __restrict__ conv_w,
                                                        const float* __restrict__ img_w) {
    __shared__ float As[8][128];   // [mm][o]
    __shared__ float Bs[8][132];   // [mm][k]
    const int l = blockIdx.y;
    const int kt = blockIdx.x * 128;
    const int tid = threadIdx.x;
    const int tm = tid >> 4, tn = tid & 15;

    float acc[8][8];
    #pragma unroll
    for (int i = 0; i < 8; i++)
        #pragma unroll
        for (int j = 0; j < 8; j++) acc[i][j] = 0.f;

    const float* cwb = conv_w + (size_t)l * MID * KDIM + kt;
    for (int m0 = 0; m0 < MID; m0 += 8) {
        #pragma unroll
        for (int q = 0; q < 4; q++) {
            int idx = tid * 4 + q;
            int mm = idx >> 7, o = idx & 127;
            As[mm][o] = __ldg(&img_w[(size_t)o * (MID*NLVL) + l*MID + m0 + mm]);
        }
        {
            int row = tid >> 5, col = (tid & 31) * 4;
            float4 v = __ldg((const float4*)&cwb[(size_t)(m0 + row) * KDIM + col]);
            Bs[row][col] = v.x; Bs[row][col+1] = v.y; Bs[row][col+2] = v.z; Bs[row][col+3] = v.w;
        }
        __syncthreads();
        #pragma unroll
        for (int mm = 0; mm < 8; mm++) {
            float a[8], b[8];
            #pragma unroll
            for (int i = 0; i < 8; i++) a[i] = As[mm][tm*8 + i];
            #pragma unroll
            for (int j = 0; j < 8; j++) b[j] = Bs[mm][tn*8 + j];
            #pragma unroll
            for (int i = 0; i < 8; i++)
                #pragma unroll
                for (int j = 0; j < 8; j++) acc[i][j] += a[i] * b[j];
        }
        __syncthreads();
    }
    #pragma unroll
    for (int i = 0; i < 8; i++) {
        int o = tm*8 + i;
        char* obase = (char*)g_w + (size_t)l * NCHUNK * 16384 + o*128;
        uint32_t sw = (uint32_t)((o & 7) << 4);
        #pragma unroll
        for (int j = 0; j < 8; j++) {
            int k = kt + tn*8 + j;
            int ci = k / 9, rs = k - ci * 9;
            int kn = rs * 256 + ci;
            int chunk = kn >> 6, kk = kn & 63;
            *(__half*)(obase + (size_t)chunk * 16384 + (((uint32_t)(kk*2)) ^ sw)) = __float2half(acc[i][j]);
        }
    }
}

// ---------------- c2 (folded conv bias) + stats zeroing ----------------
__global__ void c2_kernel(const float* __restrict__ img_w, const float* __restrict__ conv_b) {
    int l = blockIdx.x, o = threadIdx.x;
    if (l == 0) {
        #pragma unroll
        for (int j = 0; j < 4; j++) g_stats[j*128 + o] = 0.0;
    }
    const float* iw = img_w + (size_t)o*(MID*NLVL) + l*MID;
    float c = 0.f;
    for (int m = 0; m < MID; m++) c += iw[m] * conv_b[l*MID + m];
    g_c2[l*OUTC + o] = c;
}

// ---------------- pts_w -> fp16 pre-swizzled chunk tiles (8KB: row o = 64B, (o&3)<<4) ----------------
__global__ void pts_fold_kernel(const float* __restrict__ pts_w) {
    int idx = blockIdx.x * blockDim.x + threadIdx.x;   // 16384
    int o = idx >> 7, k = idx & 127;
    __half h = __float2half(__ldg(&pts_w[o*PTSC + k]));
    int chunk = k >> 5, kk = k & 31;
    *(__half*)((char*)g_pw + chunk*8192 + o*64 + (((kk*2)) ^ ((o & 3) << 4))) = h;
}

// ---------------- conv: 4 warps, 64x64 warp tiles (fp16, fully-async staging, 3-stage, 2 CTA/SM) --------
__global__ __launch_bounds__(128, 2) void conv_mma_kernel() {
    extern __shared__ char smem_raw[];
    uint32_t raw = smem_u32(smem_raw);
    uint32_t sb = (raw + 1023u) & ~1023u;

    const int l = blockIdx.z, n = blockIdx.y;
    const int m0 = blockIdx.x * 128;
    const int tid = threadIdx.x, wid = tid >> 5, lane = tid & 31;
    const int warp_m = wid & 1, warp_n = wid >> 1;

    const __half* imgT = g_imgT + (size_t)(l*NIMG + n) * NPIX * CIN;
    const char* wb = (const char*)g_w + (size_t)l * NCHUNK * 16384;

    // staging identity: thread = full A row p_local (128B)
    const int p_local = tid;
    const int P = m0 + p_local;
    const int ypix = P / WW, xpix = P % WW;
    const uint32_t arow = (uint32_t)(p_local * 128);
    const uint32_t axor = (uint32_t)((p_local & 7) << 4);

    uint32_t vmask = 0;
    #pragma unroll
    for (int rs = 0; rs < 9; rs++) {
        int r = rs / 3 - 1, s = rs % 3 - 1;
        int ym = ypix + r, xm = xpix + s;
        if ((unsigned)ym < HH && (unsigned)xm < WW) vmask |= (1u << rs);
    }

    float acc[4][8][4];
    #pragma unroll
    for (int i = 0; i < 4; i++)
        #pragma unroll
        for (int j = 0; j < 8; j++)
            #pragma unroll
            for (int q = 0; q < 4; q++) acc[i][j][q] = 0.f;

    auto issue = [&](int c, int buf) {
        int rs = c >> 2, ci0 = (c & 3) << 6;
        int spix = P + c_tapoff[rs];
        spix = spix < 0 ? 0 : (spix > NPIX-1 ? NPIX-1 : spix);
        uint32_t sz = ((vmask >> rs) & 1) ? 16u : 0u;
        const char* asrc = (const char*)(imgT + (size_t)spix * CIN + ci0);
        uint32_t adst = sb + (uint32_t)buf * STAGE + arow;
        #pragma unroll
        for (int q = 0; q < 8; q++) {
            uint32_t s16 = (uint32_t)(q * 16);
            CP_ASYNC16Z(adst + (s16 ^ axor), asrc + q * 16, sz);
        }
        uint32_t bdst = sb + (uint32_t)buf * STAGE + 16384u;
        const char* bsrc = wb + (size_t)c * 16384;
        #pragma unroll
        for (int j = 0; j < 8; j++) {
            uint32_t off = (uint32_t)((j*128 + tid) * 16);
            CP_ASYNC16(bdst + off, bsrc + off);
        }
        CP_COMMIT();
    };

    const int ar0 = warp_m * 64 + (lane & 15);
    const int br0 = warp_n * 64 + (lane & 15);
    const uint32_t ax = (uint32_t)((ar0 & 7) << 4);
    const uint32_t kh = (uint32_t)((lane >> 4) << 4);
    auto compute = [&](int buf) {
        uint32_t st = sb + (uint32_t)buf * STAGE;
        uint32_t aB = st, bB = st + 16384u;
        #pragma unroll
        for (int s = 0; s < 4; s++) {
            uint32_t kb = (uint32_t)(s * 32) + kh;
            uint32_t bh[4][4];
            #pragma unroll
            for (int jb = 0; jb < 4; jb++) {
                uint32_t row = (uint32_t)(br0 + jb*16);
                LDSM4(bh[jb], bB + row*128 + (kb ^ ((row & 7) << 4)));
            }
            #pragma unroll
            for (int mi = 0; mi < 4; mi++) {
                uint32_t ahr[4];
                LDSM4(ahr, aB + (uint32_t)((ar0 + mi*16) * 128) + (kb ^ ax));
                #pragma unroll
                for (int jb = 0; jb < 4; jb++) {
                    MMAH16816(acc[mi][jb*2+0], ahr, bh[jb][0], bh[jb][2]);
                    MMAH16816(acc[mi][jb*2+1], ahr, bh[jb][1], bh[jb][3]);
                }
            }
        }
    };

    issue(0, 0);
    issue(1, 1);
    int buf = 0;
    for (int c = 0; c < NCHUNK; c++) {
        if (c + 1 < NCHUNK) { asm volatile("cp.async.wait_group 1;" ::: "memory"); }
        else                { asm volatile("cp.async.wait_group 0;" ::: "memory"); }
        __syncthreads();
        if (c + 2 < NCHUNK) {
            int nb = buf + 2; if (nb >= 3) nb -= 3;
            issue(c + 2, nb);
        }
        compute(buf);
        if (++buf == 3) buf = 0;
    }

    // ---- writeback (fp16) ----
    __half* ob = g_conv + ((size_t)(l*NIMG + n) * NPIX + m0) * OUTC;
    const int mrow = warp_m * 64 + (lane >> 2);
    const int ncol = warp_n * 64 + (lane & 3) * 2;
    #pragma unroll
    for (int mi = 0; mi < 4; mi++) {
        #pragma unroll
        for (int nj = 0; nj < 8; nj++) {
            int m = mrow + mi*16;
            int o = ncol + nj*8;
            *(__half2*)&ob[(size_t)m*OUTC + o]     = __floats2half2_rn(acc[mi][nj][0], acc[mi][nj][1]);
            *(__half2*)&ob[(size_t)(m+8)*OUTC + o] = __floats2half2_rn(acc[mi][nj][2], acc[mi][nj][3]);
        }
    }
}

// ---------------- pts branch GEMM via fp16 2-pass mma: [131072,128] x [128,128] ----------------
__global__ __launch_bounds__(256, 2) void ptsgemm_mma_kernel(const float* __restrict__ A) {
    __shared__ __align__(1024) char psm[24576];
    uint32_t sb = smem_u32(psm);

    const int m0 = blockIdx.x * 128;
    const int tid = threadIdx.x, wid = tid >> 5, lane = tid & 31;
    const int warp_m = wid >> 2, warp_n = wid & 3;

    const int p_local = tid >> 1, hhalf = tid & 1;
    const uint32_t arow = (uint32_t)(p_local * 128);
    const uint32_t axor = (uint32_t)((p_local & 7) << 4);
    const float* ag = A + (size_t)(m0 + p_local) * PTSC;

    float acc[4][4][4];
    #pragma unroll
    for (int i = 0; i < 4; i++)
        #pragma unroll
        for (int j = 0; j < 4; j++)
            #pragma unroll
            for (int q = 0; q < 4; q++) acc[i][j][q] = 0.f;

    const int ar0 = warp_m * 64 + (lane & 15);
    const int br0 = warp_n * 32 + (lane & 15);
    const uint32_t ax = (uint32_t)((ar0 & 7) << 4);
    const uint32_t kh = (uint32_t)((lane >> 4) << 4);

    for (int c = 0; c < 4; c++) {
        #pragma unroll
        for (int j = 0; j < 2; j++) {
            uint32_t off = (uint32_t)((j*256 + tid) * 16);
            CP_ASYNC16(sb + 16384u + off, (const char*)g_pw + c*8192 + off);
        }
        CP_COMMIT();
        const float* src = ag + c*32 + hhalf*16;
        #pragma unroll
        for (int j = 0; j < 8; j++) {
            float v0 = src[2*j], v1 = src[2*j+1];
            __half h0 = __float2half(v0), h1 = __float2half(v1);
            float l0 = v0 - __half2float(h0);
            float l1 = v1 - __half2float(h1);
            uint32_t hpair = (uint32_t)__half_as_ushort(h0) | ((uint32_t)__half_as_ushort(h1) << 16);
            uint32_t lpair;
            asm("cvt.rn.f16x2.f32 %0, %1, %2;" : "=r"(lpair) : "f"(l1), "f"(l0));
            uint32_t colb = (uint32_t)(hhalf * 32 + 4*j);
            *(uint32_t*)(psm + arow + (colb ^ axor))        = hpair;
            *(uint32_t*)(psm + arow + ((64 + colb) ^ axor)) = lpair;
        }
        CP_WAIT0();
        __syncthreads();
        #pragma unroll
        for (int s = 0; s < 2; s++) {
            uint32_t kb = (uint32_t)(s * 32) + kh;
            uint32_t bh[2][4];
            #pragma unroll
            for (int jb = 0; jb < 2; jb++) {
                uint32_t row = (uint32_t)(br0 + jb*16);
                LDSM4(bh[jb], sb + 16384u + row*64 + (kb ^ ((row & 3) << 4)));
            }
            #pragma unroll
            for (int mi = 0; mi < 4; mi++) {
                uint32_t aoff = (uint32_t)((ar0 + mi*16) * 128);
                uint32_t ahr[4], alr[4];
                LDSM4(ahr, sb + aoff + (kb ^ ax));
                LDSM4(alr, sb + aoff + ((64 + kb) ^ ax));
                #pragma unroll
                for (int ni = 0; ni < 4; ni++) {
                    int jb = ni >> 1, sel = ni & 1;
                    MMAH16816(acc[mi][ni], ahr, bh[jb][sel], bh[jb][sel+2]);
                    MMAH16816(acc[mi][ni], alr, bh[jb][sel], bh[jb][sel+2]);
                }
            }
        }
        __syncthreads();
    }

    __half* ob = g_ypts + (size_t)m0 * OUTC;
    const int mrow = warp_m * 64 + (lane >> 2);
    const int ncol = warp_n * 32 + (lane & 3) * 2;
    #pragma unroll
    for (int mi = 0; mi < 4; mi++) {
        #pragma unroll
        for (int ni = 0; ni < 4; ni++) {
            int m = mrow + mi*16;
            int o = ncol + ni*8;
            *(__half2*)&ob[(size_t)m*OUTC + o]     = __floats2half2_rn(acc[mi][ni][0], acc[mi][ni][1]);
            *(__half2*)&ob[(size_t)(m+8)*OUTC + o] = __floats2half2_rn(acc[mi][ni][2], acc[mi][ni][3]);
        }
    }
}

// ---------------- projection + bilinear gather (warp per point, fp16 in/out) ----------------
__global__ __launch_bounds__(256) void sample_kernel(const float* __restrict__ pts_xyz,
                                                     const int* __restrict__ cam_ids,
                                                     const float* __restrict__ T,
                                                     const float* __restrict__ Kmat) {
    int gw = (blockIdx.x * blockDim.x + threadIdx.x) >> 5;
    int lane = threadIdx.x & 31;
    if (gw >= TOTPTS) return;
    int p = gw;
    int b = p >> 16;
    int cam = __ldg(&cam_ids[p]);
    float x = __ldg(&pts_xyz[p*3+0]);
    float y = __ldg(&pts_xyz[p*3+1]);
    float z = __ldg(&pts_xyz[p*3+2]);
    const float* t = T + cam*16;
    float pcx = t[0]*x + t[1]*y + t[2]*z  + t[3];
    float pcy = t[4]*x + t[5]*y + t[6]*z  + t[7];
    float pcz = t[8]*x + t[9]*y + t[10]*z + t[11];
    const float* km = Kmat + cam*9;
    float pim0 = (km[0]*0.125f)*pcx + km[1]*pcy + (km[2]*0.125f)*pcz;
    float pim1 = km[3]*pcx + (km[4]*0.125f)*pcy + (km[5]*0.125f)*pcz;
    float pim2 = km[6]*pcx + km[7]*pcy + km[8]*pcz;
    float u = pim0 / pim2, v = pim1 / pim2;
    float px = u * ((float)(WW-1)/(float)WW);
    float py = v * ((float)(HH-1)/(float)HH);
    float x0 = floorf(px), y0 = floorf(py);
    float wx1 = px - x0, wy1 = py - y0;
    float wx0 = 1.f - wx1, wy0 = 1.f - wy1;

    float xs[2] = {x0, x0 + 1.f};
    float ys[2] = {y0, y0 + 1.f};
    float wxs[2] = {wx0, wx1};
    float wys[2] = {wy0, wy1};
    float cw[4];
    int   cox[4], coy[4];
    float wsum = 0.f;
    #pragma unroll
    for (int cy = 0; cy < 2; cy++)
        #pragma unroll
        for (int cx = 0; cx < 2; cx++) {
            float xf = xs[cx], yf = ys[cy];
            bool valid = (xf >= 0.f) & (xf <= (float)(WW-1)) & (yf >= 0.f) & (yf <= (float)(HH-1));
            float w = valid ? (wxs[cx] * wys[cy]) : 0.f;
            cw[cy*2+cx] = w;
            wsum += w;
            cox[cy*2+cx] = (int)fminf(fmaxf(xf, 0.f), (float)(WW-1));
            coy[cy*2+cx] = (int)fminf(fmaxf(yf, 0.f), (float)(HH-1));
        }

    int img = b * NCAMS + cam;
    float4 acc = make_float4(0.f, 0.f, 0.f, 0.f);
    #pragma unroll
    for (int l = 0; l < NLVL; l++) {
        const __half* basep = g_conv + (size_t)(l*NIMG + img) * NPIX * OUTC;
        #pragma unroll
        for (int c = 0; c < 4; c++) {
            float w = cw[c];
            if (w != 0.f) {
                const uint2* src = (const uint2*)(basep + ((size_t)coy[c]*WW + cox[c]) * OUTC) + lane;
                uint2 d = __ldg(src);
                float2 f0 = __half22float2(*(__half2*)&d.x);
                float2 f1 = __half22float2(*(__half2*)&d.y);
                acc.x += w * f0.x; acc.y += w * f0.y; acc.z += w * f1.x; acc.w += w * f1.y;
            }
        }
        float4 c2v = __ldg((const float4*)(g_c2 + l*OUTC) + lane);
        acc.x += wsum * c2v.x; acc.y += wsum * c2v.y; acc.z += wsum * c2v.z; acc.w += wsum * c2v.w;
    }
    __half2 o0 = __floats2half2_rn(acc.x, acc.y);
    __half2 o1 = __floats2half2_rn(acc.z, acc.w);
    uint2 packed = make_uint2(*(uint32_t*)&o0, *(uint32_t*)&o1);
    ((uint2*)(g_yimg + (size_t)p * OUTC))[lane] = packed;
}

// ---------------- BN statistics (both branches, fp16 inputs) ----------------
__global__ void stats_kernel() {
    int o = threadIdx.x;                 // 0..127
    size_t r0 = (size_t)blockIdx.x * 256;
    float si = 0.f, qi = 0.f, sp = 0.f, qp = 0.f;
    for (int r = 0; r < 256; r++) {
        float vi = __half2float(g_yimg[(r0 + r) * OUTC + o]);
        float vp = __half2float(g_ypts[(r0 + r) * OUTC + o]);
        si += vi; qi += vi * vi;
        sp += vp; qp += vp * vp;
    }
    atomicAdd(&g_stats[o],          (double)si);
    atomicAdd(&g_stats[OUTC + o],   (double)qi);
    atomicAdd(&g_stats[2*OUTC + o], (double)sp);
    atomicAdd(&g_stats[3*OUTC + o], (double)qp);
}

__global__ void bnparams_kernel(const float* __restrict__ gi, const float* __restrict__ bi,
                                const float* __restrict__ gp, const float* __restrict__ bp) {
    int o = threadIdx.x;
    double n = (double)TOTPTS;
    double mi = g_stats[o] / n;
    double vi = g_stats[OUTC + o] / n - mi * mi;
    float s = gi[o] / sqrtf((float)vi + 1e-3f);
    g_bn[o] = s;
    g_bn[OUTC + o] = bi[o] - (float)mi * s;
    double mp = g_stats[2*OUTC + o] / n;
    double vp = g_stats[3*OUTC + o] / n - mp * mp;
    float s2 = gp[o] / sqrtf((float)vp + 1e-3f);
    g_bn[2*OUTC + o] = s2;
    g_bn[3*OUTC + o] = bp[o] - (float)mp * s2;
}

// ---------------- finalize: relu(BN(img) + BN(pts)) (fp16 inputs, fp32 output) ----------------
__global__ __launch_bounds__(256) void finalize_kernel(float* __restrict__ out) {
    size_t idx = (size_t)blockIdx.x * blockDim.x + threadIdx.x;   // 4-element group index
    int o = (int)(idx & 31) * 4;
    uint2 di = ((const uint2*)g_yimg)[idx];
    uint2 dp = ((const uint2*)g_ypts)[idx];
    float2 yi0 = __half22float2(*(__half2*)&di.x);
    float2 yi1 = __half22float2(*(__half2*)&di.y);
    float2 yp0 = __half22float2(*(__half2*)&dp.x);
    float2 yp1 = __half22float2(*(__half2*)&dp.y);
    float si0 = g_bn[o], si1 = g_bn[o+1], si2 = g_bn[o+2], si3 = g_bn[o+3];
    float ti0 = g_bn[OUTC+o], ti1 = g_bn[OUTC+o+1], ti2 = g_bn[OUTC+o+2], ti3 = g_bn[OUTC+o+3];
    float sp0 = g_bn[2*OUTC+o], sp1 = g_bn[2*OUTC+o+1], sp2 = g_bn[2*OUTC+o+2], sp3 = g_bn[2*OUTC+o+3];
    float tp0 = g_bn[3*OUTC+o], tp1 = g_bn[3*OUTC+o+1], tp2 = g_bn[3*OUTC+o+2], tp3 = g_bn[3*OUTC+o+3];
    float4 r;
    r.x = fmaxf(yi0.x*si0 + ti0 + yp0.x*sp0 + tp0, 0.f);
    r.y = fmaxf(yi0.y*si1 + ti1 + yp0.y*sp1 + tp1, 0.f);
    r.z = fmaxf(yi1.x*si2 + ti2 + yp1.x*sp2 + tp2, 0.f);
    r.w = fmaxf(yi1.y*si3 + ti3 + yp1.y*sp3 + tp3, 0.f);
    ((float4*)out)[idx] = r;
}

// ---------------- launch ----------------
#define CONV_SMEM (1024 + 3*STAGE)   /* align slack + 3 stages = 99328 */

extern "C" void kernel_launch(void* const* d_in, const int* in_sizes, int n_in,
                              void* d_out, int out_size) {
    const float* img_feats = (const float*)d_in[0];
    const float* pts_xyz   = (const float*)d_in[1];
    const float* pts_feats = (const float*)d_in[2];
    const float* T         = (const float*)d_in[3];
    const float* Kmat      = (const float*)d_in[4];
    const float* conv_w    = (const float*)d_in[5];
    const float* conv_b    = (const float*)d_in[6];
    const float* img_w     = (const float*)d_in[7];
    // d_in[8] img_b: cancels exactly under batch-norm
    const float* img_gamma = (const float*)d_in[9];
    const float* img_beta  = (const float*)d_in[10];
    const float* pts_w     = (const float*)d_in[11];
    // d_in[12] pts_b: cancels exactly under batch-norm
    const float* pts_gamma = (const float*)d_in[13];
    const float* pts_beta  = (const float*)d_in[14];
    const int*   cam_ids   = (const int*)d_in[15];
    float* out = (float*)d_out;
    (void)in_sizes; (void)n_in; (void)out_size;

    cudaFuncSetAttribute(conv_mma_kernel, cudaFuncAttributeMaxDynamicSharedMemorySize, CONV_SMEM);

    transpose_kernel<<<dim3(NPIX/32, CIN/64, NLVL*NIMG), 256>>>(img_feats);
    fold_gemm_kernel<<<dim3(KDIM/128, NLVL), 256>>>(conv_w, img_w);
    c2_kernel<<<NLVL, 128>>>(img_w, conv_b);
    pts_fold_kernel<<<(PTSC*OUTC)/256, 256>>>(pts_w);
    conv_mma_kernel<<<dim3(NPIX/128, NIMG, NLVL), 128, CONV_SMEM>>>();
    sample_kernel<<<(TOTPTS*32)/256, 256>>>(pts_xyz, cam_ids, T, Kmat);
    ptsgemm_mma_kernel<<<TOTPTS/128, 256>>>(pts_feats);
    stats_kernel<<<TOTPTS/256, 128>>>();
    bnparams_kernel<<<1, 128>>>(img_gamma, img_beta, pts_gamma, pts_beta);
    finalize_kernel<<<(size_t)TOTPTS*OUTC/4/256, 256>>>(out);
}

// round 15
// speedup vs baseline: 1.1524x; 1.1524x over previous
#include <cuda_runtime.h>
#include <cuda_fp16.h>
#include <math.h>
#include <stdint.h>

#define NLVL 3
#define BATCH 2
#define NPTSB 65536
#define NCAMS 5
#define CIN 256
#define MID 128
#define OUTC 128
#define PTSC 128
#define HH 64
#define WW 112
#define NIMG (BATCH*NCAMS)          /* 10 */
#define NPIX (HH*WW)                /* 7168 */
#define KDIM (CIN*9)                /* 2304 */
#define TOTPTS (BATCH*NPTSB)        /* 131072 */
#define KCH 64                      /* K elements per pipeline chunk */
#define NCHUNK (KDIM/KCH)           /* 36 */
#define STAGE 32768                 /* A 16KB fp16 + B 16KB fp16 */

// ---------------- scratch (static device arrays) ----------------
__device__ float  g_c2[NLVL*OUTC];                             // folded conv bias [l][o]
__device__ __half g_w[(size_t)NLVL*NCHUNK*8192];               // folded conv weights fp16 (tap-major k), pre-swizzled 16KB tiles
__device__ __half g_pw[4*4096];                                // pts_w fp16, pre-swizzled 8KB chunk tiles
__device__ __half g_imgT[(size_t)NLVL*NIMG*NPIX*CIN];          // transposed+fp16 image [l][n][pix][ci]
__device__ __half g_conv[(size_t)NLVL*NIMG*NPIX*OUTC];         // projected conv features (fp16)
__device__ __half g_yimg[(size_t)TOTPTS*OUTC];                 // img branch pre-BN (fp16)
__device__ __half g_ypts[(size_t)TOTPTS*OUTC];                 // pts branch pre-BN (fp16)
__device__ double g_stats[4*OUTC];
__device__ float  g_bn[4*OUTC];

__constant__ int c_tapoff[9] = {-WW-1, -WW, -WW+1, -1, 0, 1, WW-1, WW, WW+1};

// ---------------- PTX helpers ----------------
__device__ __forceinline__ uint32_t smem_u32(const void* p) {
    uint32_t a;
    asm("{ .reg .u64 t; cvta.to.shared.u64 t, %1; cvt.u32.u64 %0, t; }" : "=r"(a) : "l"(p));
    return a;
}
#define LDSM4(r, addr) \
    asm volatile("ldmatrix.sync.aligned.m8n8.x4.shared.b16 {%0,%1,%2,%3}, [%4];" \
        : "=r"((r)[0]), "=r"((r)[1]), "=r"((r)[2]), "=r"((r)[3]) : "r"(addr))
#define MMAH16816(c, a, b0, b1) \
    asm volatile("mma.sync.aligned.m16n8k16.row.col.f32.f16.f16.f32 " \
        "{%0,%1,%2,%3}, {%4,%5,%6,%7}, {%8,%9}, {%0,%1,%2,%3};" \
        : "+f"((c)[0]), "+f"((c)[1]), "+f"((c)[2]), "+f"((c)[3]) \
        : "r"((a)[0]), "r"((a)[1]), "r"((a)[2]), "r"((a)[3]), "r"(b0), "r"(b1))
#define CP_ASYNC16(dst, src) \
    asm volatile("cp.async.cg.shared.global [%0], [%1], 16;" :: "r"(dst), "l"(src))
#define CP_ASYNC16Z(dst, src, sz) \
    asm volatile("cp.async.cg.shared.global [%0], [%1], 16, %2;" :: "r"(dst), "l"(src), "r"(sz))
#define CP_COMMIT() asm volatile("cp.async.commit_group;")
#define CP_WAIT0()  asm volatile("cp.async.wait_group 0;" ::: "memory")

// ---------------- transpose + fp16 convert: img[l][n][ci][pix] -> g_imgT[l][n][pix][ci] ----------------
__global__ __launch_bounds__(256) void transpose_kernel(const float* __restrict__ img) {
    __shared__ float t[64][33];
    const int zi = blockIdx.z;
    const int p0 = blockIdx.x * 32, c0 = blockIdx.y * 64;
    const float* src = img + (size_t)zi * CIN * NPIX;
    const int tx = threadIdx.x & 31, ty = threadIdx.x >> 5;   // ty 0..7
    #pragma unroll
    for (int j = 0; j < 8; j++)
        t[ty*8 + j][tx] = __ldg(&src[(size_t)(c0 + ty*8 + j) * NPIX + p0 + tx]);
    __syncthreads();
    __half* dst = g_imgT + (size_t)zi * NPIX * CIN;
    const int pp = threadIdx.x >> 3;        // 0..31 pixel
    const int cc = threadIdx.x & 7;         // 8-channel group
    uint32_t pk[4];
    #pragma unroll
    for (int q = 0; q < 4; q++) {
        __half2 h = __floats2half2_rn(t[cc*8 + 2*q][pp], t[cc*8 + 2*q + 1][pp]);
        pk[q] = *(uint32_t*)&h;
    }
    *(uint4*)&dst[(size_t)(p0 + pp) * CIN + c0 + cc*8] = make_uint4(pk[0], pk[1], pk[2], pk[3]);
}

// ---------------- fold as tiled GEMM: W2[l][o][k] = sum_m img_w[o][l*128+m] * conv_w[l][m][k] ----------------
__global__ __launch_bounds__(256) void fold_gemm_kernel(const float* __restrict__ conv_w,
                                                        const float* __restrict__ img_w) {
    __shared__ float As[8][128];   // [mm][o]
    __shared__ float Bs[8][132];   // [mm][k]
    const int l = blockIdx.y;
    const int kt = blockIdx.x * 128;
    const int tid = threadIdx.x;
    const int tm = tid >> 4, tn = tid & 15;

    float acc[8][8];
    #pragma unroll
    for (int i = 0; i < 8; i++)
        #pragma unroll
        for (int j = 0; j < 8; j++) acc[i][j] = 0.f;

    const float* cwb = conv_w + (size_t)l * MID * KDIM + kt;
    for (int m0 = 0; m0 < MID; m0 += 8) {
        #pragma unroll
        for (int q = 0; q < 4; q++) {
            int idx = tid * 4 + q;
            int mm = idx >> 7, o = idx & 127;
            As[mm][o] = __ldg(&img_w[(size_t)o * (MID*NLVL) + l*MID + m0 + mm]);
        }
        {
            int row = tid >> 5, col = (tid & 31) * 4;
            float4 v = __ldg((const float4*)&cwb[(size_t)(m0 + row) * KDIM + col]);
            Bs[row][col] = v.x; Bs[row][col+1] = v.y; Bs[row][col+2] = v.z; Bs[row][col+3] = v.w;
        }
        __syncthreads();
        #pragma unroll
        for (int mm = 0; mm < 8; mm++) {
            float a[8], b[8];
            #pragma unroll
            for (int i = 0; i < 8; i++) a[i] = As[mm][tm*8 + i];
            #pragma unroll
            for (int j = 0; j < 8; j++) b[j] = Bs[mm][tn*8 + j];
            #pragma unroll
            for (int i = 0; i < 8; i++)
                #pragma unroll
                for (int j = 0; j < 8; j++) acc[i][j] += a[i] * b[j];
        }
        __syncthreads();
    }
    #pragma unroll
    for (int i = 0; i < 8; i++) {
        int o = tm*8 + i;
        char* obase = (char*)g_w + (size_t)l * NCHUNK * 16384 + o*128;
        uint32_t sw = (uint32_t)((o & 7) << 4);
        #pragma unroll
        for (int j = 0; j < 8; j++) {
            int k = kt + tn*8 + j;
            int ci = k / 9, rs = k - ci * 9;
            int kn = rs * 256 + ci;
            int chunk = kn >> 6, kk = kn & 63;
            *(__half*)(obase + (size_t)chunk * 16384 + (((uint32_t)(kk*2)) ^ sw)) = __float2half(acc[i][j]);
        }
    }
}

// ---------------- c2 (folded conv bias) + stats zeroing ----------------
__global__ void c2_kernel(const float* __restrict__ img_w, const float* __restrict__ conv_b) {
    int l = blockIdx.x, o = threadIdx.x;
    if (l == 0) {
        #pragma unroll
        for (int j = 0; j < 4; j++) g_stats[j*128 + o] = 0.0;
    }
    const float* iw = img_w + (size_t)o*(MID*NLVL) + l*MID;
    float c = 0.f;
    for (int m = 0; m < MID; m++) c += iw[m] * conv_b[l*MID + m];
    g_c2[l*OUTC + o] = c;
}

// ---------------- pts_w -> fp16 pre-swizzled chunk tiles (8KB: row o = 64B, (o&3)<<4) ----------------
__global__ void pts_fold_kernel(const float* __restrict__ pts_w) {
    int idx = blockIdx.x * blockDim.x + threadIdx.x;   // 16384
    int o = idx >> 7, k = idx & 127;
    __half h = __float2half(__ldg(&pts_w[o*PTSC + k]));
    int chunk = k >> 5, kk = k & 31;
    *(__half*)((char*)g_pw + chunk*8192 + o*64 + (((kk*2)) ^ ((o & 3) << 4))) = h;
}

// ---------------- mma.sync conv as 9 shifted GEMMs (fp16, fully-async staging, 3-stage, 2 CTA/SM) --------
__global__ __launch_bounds__(256, 2) void conv_mma_kernel() {
    extern __shared__ char smem_raw[];
    uint32_t raw = smem_u32(smem_raw);
    uint32_t sb = (raw + 1023u) & ~1023u;

    const int l = blockIdx.z, n = blockIdx.y;
    const int m0 = blockIdx.x * 128;
    const int tid = threadIdx.x, wid = tid >> 5, lane = tid & 31;
    const int warp_m = wid >> 2, warp_n = wid & 3;

    const __half* imgT = g_imgT + (size_t)(l*NIMG + n) * NPIX * CIN;
    const char* wb = (const char*)g_w + (size_t)l * NCHUNK * 16384;

    const int p_local = tid >> 1, hhalf = tid & 1;
    const int P = m0 + p_local;
    const int ypix = P / WW, xpix = P % WW;
    const uint32_t arow = (uint32_t)(p_local * 128);
    const uint32_t axor = (uint32_t)((p_local & 7) << 4);

    uint32_t vmask = 0;
    #pragma unroll
    for (int rs = 0; rs < 9; rs++) {
        int r = rs / 3 - 1, s = rs % 3 - 1;
        int ym = ypix + r, xm = xpix + s;
        if ((unsigned)ym < HH && (unsigned)xm < WW) vmask |= (1u << rs);
    }

    float acc[4][4][4];
    #pragma unroll
    for (int i = 0; i < 4; i++)
        #pragma unroll
        for (int j = 0; j < 4; j++)
            #pragma unroll
            for (int q = 0; q < 4; q++) acc[i][j][q] = 0.f;

    auto issue = [&](int c, int buf) {
        int rs = c >> 2, ci0 = (c & 3) << 6;
        int spix = P + c_tapoff[rs];
        spix = spix < 0 ? 0 : (spix > NPIX-1 ? NPIX-1 : spix);
        uint32_t sz = ((vmask >> rs) & 1) ? 16u : 0u;
        const char* asrc = (const char*)(imgT + (size_t)spix * CIN + ci0) + hhalf * 64;
        uint32_t adst = sb + (uint32_t)buf * STAGE + arow;
        #pragma unroll
        for (int q = 0; q < 4; q++) {
            uint32_t s16 = (uint32_t)(hhalf * 64 + q * 16);
            CP_ASYNC16Z(adst + (s16 ^ axor), asrc + q * 16, sz);
        }
        uint32_t bdst = sb + (uint32_t)buf * STAGE + 16384u;
        const char* bsrc = wb + (size_t)c * 16384;
        #pragma unroll
        for (int j = 0; j < 4; j++) {
            uint32_t off = (uint32_t)((j*256 + tid) * 16);
            CP_ASYNC16(bdst + off, bsrc + off);
        }
        CP_COMMIT();
    };

    const int ar0 = warp_m * 64 + (lane & 15);
    const int br0 = warp_n * 32 + (lane & 15);
    const uint32_t ax = (uint32_t)((ar0 & 7) << 4);
    const uint32_t kh = (uint32_t)((lane >> 4) << 4);
    auto compute = [&](int buf) {
        uint32_t st = sb + (uint32_t)buf * STAGE;
        uint32_t aB = st, bB = st + 16384u;
        #pragma unroll
        for (int s = 0; s < 4; s++) {
            uint32_t kb = (uint32_t)(s * 32) + kh;
            uint32_t bh[2][4];
            #pragma unroll
            for (int jb = 0; jb < 2; jb++) {
                uint32_t row = (uint32_t)(br0 + jb*16);
                LDSM4(bh[jb], bB + row*128 + (kb ^ ((row & 7) << 4)));
            }
            #pragma unroll
            for (int mi = 0; mi < 4; mi++) {
                uint32_t ahr[4];
                LDSM4(ahr, aB + (uint32_t)((ar0 + mi*16) * 128) + (kb ^ ax));
                #pragma unroll
                for (int ni = 0; ni < 4; ni++) {
                    int jb = ni >> 1, sel = ni & 1;
                    MMAH16816(acc[mi][ni], ahr, bh[jb][sel], bh[jb][sel+2]);
                }
            }
        }
    };

    issue(0, 0);
    issue(1, 1);
    int buf = 0;
    for (int c = 0; c < NCHUNK; c++) {
        if (c + 1 < NCHUNK) { asm volatile("cp.async.wait_group 1;" ::: "memory"); }
        else                { asm volatile("cp.async.wait_group 0;" ::: "memory"); }
        __syncthreads();
        if (c + 2 < NCHUNK) {
            int nb = buf + 2; if (nb >= 3) nb -= 3;
            issue(c + 2, nb);
        }
        compute(buf);
        if (++buf == 3) buf = 0;
    }

    // ---- writeback (fp16) ----
    __half* ob = g_conv + ((size_t)(l*NIMG + n) * NPIX + m0) * OUTC;
    const int mrow = warp_m * 64 + (lane >> 2);
    const int ncol = warp_n * 32 + (lane & 3) * 2;
    #pragma unroll
    for (int mi = 0; mi < 4; mi++) {
        #pragma unroll
        for (int ni = 0; ni < 4; ni++) {
            int m = mrow + mi*16;
            int o = ncol + ni*8;
            *(__half2*)&ob[(size_t)m*OUTC + o]     = __floats2half2_rn(acc[mi][ni][0], acc[mi][ni][1]);
            *(__half2*)&ob[(size_t)(m+8)*OUTC + o] = __floats2half2_rn(acc[mi][ni][2], acc[mi][ni][3]);
        }
    }
}

// ---------------- pts branch GEMM via fp16 2-pass mma: [131072,128] x [128,128] ----------------
__global__ __launch_bounds__(256, 2) void ptsgemm_mma_kernel(const float* __restrict__ A) {
    __shared__ __align__(1024) char psm[24576];
    uint32_t sb = smem_u32(psm);

    const int m0 = blockIdx.x * 128;
    const int tid = threadIdx.x, wid = tid >> 5, lane = tid & 31;
    const int warp_m = wid >> 2, warp_n = wid & 3;

    const int p_local = tid >> 1, hhalf = tid & 1;
    const uint32_t arow = (uint32_t)(p_local * 128);
    const uint32_t axor = (uint32_t)((p_local & 7) << 4);
    const float* ag = A + (size_t)(m0 + p_local) * PTSC;

    float acc[4][4][4];
    #pragma unroll
    for (int i = 0; i < 4; i++)
        #pragma unroll
        for (int j = 0; j < 4; j++)
            #pragma unroll
            for (int q = 0; q < 4; q++) acc[i][j][q] = 0.f;

    const int ar0 = warp_m * 64 + (lane & 15);
    const int br0 = warp_n * 32 + (lane & 15);
    const uint32_t ax = (uint32_t)((ar0 & 7) << 4);
    const uint32_t kh = (uint32_t)((lane >> 4) << 4);

    for (int c = 0; c < 4; c++) {
        #pragma unroll
        for (int j = 0; j < 2; j++) {
            uint32_t off = (uint32_t)((j*256 + tid) * 16);
            CP_ASYNC16(sb + 16384u + off, (const char*)g_pw + c*8192 + off);
        }
        CP_COMMIT();
        const float* src = ag + c*32 + hhalf*16;
        #pragma unroll
        for (int j = 0; j < 8; j++) {
            float v0 = src[2*j], v1 = src[2*j+1];
            __half h0 = __float2half(v0), h1 = __float2half(v1);
            float l0 = v0 - __half2float(h0);
            float l1 = v1 - __half2float(h1);
            uint32_t hpair = (uint32_t)__half_as_ushort(h0) | ((uint32_t)__half_as_ushort(h1) << 16);
            uint32_t lpair;
            asm("cvt.rn.f16x2.f32 %0, %1, %2;" : "=r"(lpair) : "f"(l1), "f"(l0));
            uint32_t colb = (uint32_t)(hhalf * 32 + 4*j);
            *(uint32_t*)(psm + arow + (colb ^ axor))        = hpair;
            *(uint32_t*)(psm + arow + ((64 + colb) ^ axor)) = lpair;
        }
        CP_WAIT0();
        __syncthreads();
        #pragma unroll
        for (int s = 0; s < 2; s++) {
            uint32_t kb = (uint32_t)(s * 32) + kh;
            uint32_t bh[2][4];
            #pragma unroll
            for (int jb = 0; jb < 2; jb++) {
                uint32_t row = (uint32_t)(br0 + jb*16);
                LDSM4(bh[jb], sb + 16384u + row*64 + (kb ^ ((row & 3) << 4)));
            }
            #pragma unroll
            for (int mi = 0; mi < 4; mi++) {
                uint32_t aoff = (uint32_t)((ar0 + mi*16) * 128);
                uint32_t ahr[4], alr[4];
                LDSM4(ahr, sb + aoff + (kb ^ ax));
                LDSM4(alr, sb + aoff + ((64 + kb) ^ ax));
                #pragma unroll
                for (int ni = 0; ni < 4; ni++) {
                    int jb = ni >> 1, sel = ni & 1;
                    MMAH16816(acc[mi][ni], ahr, bh[jb][sel], bh[jb][sel+2]);
                    MMAH16816(acc[mi][ni], alr, bh[jb][sel], bh[jb][sel+2]);
                }
            }
        }
        __syncthreads();
    }

    __half* ob = g_ypts + (size_t)m0 * OUTC;
    const int mrow = warp_m * 64 + (lane >> 2);
    const int ncol = warp_n * 32 + (lane & 3) * 2;
    #pragma unroll
    for (int mi = 0; mi < 4; mi++) {
        #pragma unroll
        for (int ni = 0; ni < 4; ni++) {
            int m = mrow + mi*16;
            int o = ncol + ni*8;
            *(__half2*)&ob[(size_t)m*OUTC + o]     = __floats2half2_rn(acc[mi][ni][0], acc[mi][ni][1]);
            *(__half2*)&ob[(size_t)(m+8)*OUTC + o] = __floats2half2_rn(acc[mi][ni][2], acc[mi][ni][3]);
        }
    }
}

// ---------------- projection + bilinear gather (HALF-warp per point, uint4 lanes) ----------------
__global__ __launch_bounds__(256) void sample_kernel(const float* __restrict__ pts_xyz,
                                                     const int* __restrict__ cam_ids,
                                                     const float* __restrict__ T,
                                                     const float* __restrict__ Kmat) {
    int w = (blockIdx.x * blockDim.x + threadIdx.x) >> 5;      // warp id
    int lane = threadIdx.x & 31;
    int half = lane >> 4;                                      // which point in the warp
    int lane16 = lane & 15;                                    // 16B-chunk index (8 channels)
    int p = w * 2 + half;
    if (p >= TOTPTS) return;
    int b = p >> 16;
    int cam = __ldg(&cam_ids[p]);
    float x = __ldg(&pts_xyz[p*3+0]);
    float y = __ldg(&pts_xyz[p*3+1]);
    float z = __ldg(&pts_xyz[p*3+2]);
    const float* t = T + cam*16;
    float pcx = t[0]*x + t[1]*y + t[2]*z  + t[3];
    float pcy = t[4]*x + t[5]*y + t[6]*z  + t[7];
    float pcz = t[8]*x + t[9]*y + t[10]*z + t[11];
    const float* km = Kmat + cam*9;
    float pim0 = (km[0]*0.125f)*pcx + km[1]*pcy + (km[2]*0.125f)*pcz;
    float pim1 = km[3]*pcx + (km[4]*0.125f)*pcy + (km[5]*0.125f)*pcz;
    float pim2 = km[6]*pcx + km[7]*pcy + km[8]*pcz;
    float u = pim0 / pim2, v = pim1 / pim2;
    float px = u * ((float)(WW-1)/(float)WW);
    float py = v * ((float)(HH-1)/(float)HH);
    float x0 = floorf(px), y0 = floorf(py);
    float wx1 = px - x0, wy1 = py - y0;
    float wx0 = 1.f - wx1, wy0 = 1.f - wy1;

    float xs[2] = {x0, x0 + 1.f};
    float ys[2] = {y0, y0 + 1.f};
    float wxs[2] = {wx0, wx1};
    float wys[2] = {wy0, wy1};
    float cw[4];
    int   cox[4], coy[4];
    float wsum = 0.f;
    #pragma unroll
    for (int cy = 0; cy < 2; cy++)
        #pragma unroll
        for (int cx = 0; cx < 2; cx++) {
            float xf = xs[cx], yf = ys[cy];
            bool valid = (xf >= 0.f) & (xf <= (float)(WW-1)) & (yf >= 0.f) & (yf <= (float)(HH-1));
            float wgt = valid ? (wxs[cx] * wys[cy]) : 0.f;
            cw[cy*2+cx] = wgt;
            wsum += wgt;
            cox[cy*2+cx] = (int)fminf(fmaxf(xf, 0.f), (float)(WW-1));
            coy[cy*2+cx] = (int)fminf(fmaxf(yf, 0.f), (float)(HH-1));
        }

    int img = b * NCAMS + cam;
    float af[8];
    #pragma unroll
    for (int q = 0; q < 8; q++) af[q] = 0.f;
    #pragma unroll
    for (int l = 0; l < NLVL; l++) {
        const __half* basep = g_conv + (size_t)(l*NIMG + img) * NPIX * OUTC;
        #pragma unroll
        for (int c = 0; c < 4; c++) {
            float wgt = cw[c];
            if (wgt != 0.f) {
                const uint4* src = (const uint4*)(basep + ((size_t)coy[c]*WW + cox[c]) * OUTC) + lane16;
                uint4 d = __ldg(src);
                float2 f0 = __half22float2(*(__half2*)&d.x);
                float2 f1 = __half22float2(*(__half2*)&d.y);
                float2 f2 = __half22float2(*(__half2*)&d.z);
                float2 f3 = __half22float2(*(__half2*)&d.w);
                af[0] += wgt * f0.x; af[1] += wgt * f0.y;
                af[2] += wgt * f1.x; af[3] += wgt * f1.y;
                af[4] += wgt * f2.x; af[5] += wgt * f2.y;
                af[6] += wgt * f3.x; af[7] += wgt * f3.y;
            }
        }
        const float4* c2p = (const float4*)(g_c2 + l*OUTC) + lane16*2;
        float4 ca = __ldg(c2p);
        float4 cb = __ldg(c2p + 1);
        af[0] += wsum * ca.x; af[1] += wsum * ca.y; af[2] += wsum * ca.z; af[3] += wsum * ca.w;
        af[4] += wsum * cb.x; af[5] += wsum * cb.y; af[6] += wsum * cb.z; af[7] += wsum * cb.w;
    }
    __half2 h0 = __floats2half2_rn(af[0], af[1]);
    __half2 h1 = __floats2half2_rn(af[2], af[3]);
    __half2 h2 = __floats2half2_rn(af[4], af[5]);
    __half2 h3 = __floats2half2_rn(af[6], af[7]);
    ((uint4*)(g_yimg + (size_t)p * OUTC))[lane16] =
        make_uint4(*(uint32_t*)&h0, *(uint32_t*)&h1, *(uint32_t*)&h2, *(uint32_t*)&h3);
}

// ---------------- BN statistics (both branches, fp16 inputs) ----------------
__global__ void stats_kernel() {
    int o = threadIdx.x;                 // 0..127
    size_t r0 = (size_t)blockIdx.x * 256;
    float si = 0.f, qi = 0.f, sp = 0.f, qp = 0.f;
    for (int r = 0; r < 256; r++) {
        float vi = __half2float(g_yimg[(r0 + r) * OUTC + o]);
        float vp = __half2float(g_ypts[(r0 + r) * OUTC + o]);
        si += vi; qi += vi * vi;
        sp += vp; qp += vp * vp;
    }
    atomicAdd(&g_stats[o],          (double)si);
    atomicAdd(&g_stats[OUTC + o],   (double)qi);
    atomicAdd(&g_stats[2*OUTC + o], (double)sp);
    atomicAdd(&g_stats[3*OUTC + o], (double)qp);
}

__global__ void bnparams_kernel(const float* __restrict__ gi, const float* __restrict__ bi,
                                const float* __restrict__ gp, const float* __restrict__ bp) {
    int o = threadIdx.x;
    double n = (double)TOTPTS;
    double mi = g_stats[o] / n;
    double vi = g_stats[OUTC + o] / n - mi * mi;
    float s = gi[o] / sqrtf((float)vi + 1e-3f);
    g_bn[o] = s;
    g_bn[OUTC + o] = bi[o] - (float)mi * s;
    double mp = g_stats[2*OUTC + o] / n;
    double vp = g_stats[3*OUTC + o] / n - mp * mp;
    float s2 = gp[o] / sqrtf((float)vp + 1e-3f);
    g_bn[2*OUTC + o] = s2;
    g_bn[3*OUTC + o] = bp[o] - (float)mp * s2;
}

// ---------------- finalize: relu(BN(img) + BN(pts)) (fp16 inputs, fp32 output) ----------------
__global__ __launch_bounds__(256) void finalize_kernel(float* __restrict__ out) {
    size_t idx = (size_t)blockIdx.x * blockDim.x + threadIdx.x;   // 4-element group index
    int o = (int)(idx & 31) * 4;
    uint2 di = ((const uint2*)g_yimg)[idx];
    uint2 dp = ((const uint2*)g_ypts)[idx];
    float2 yi0 = __half22float2(*(__half2*)&di.x);
    float2 yi1 = __half22float2(*(__half2*)&di.y);
    float2 yp0 = __half22float2(*(__half2*)&dp.x);
    float2 yp1 = __half22float2(*(__half2*)&dp.y);
    float si0 = g_bn[o], si1 = g_bn[o+1], si2 = g_bn[o+2], si3 = g_bn[o+3];
    float ti0 = g_bn[OUTC+o], ti1 = g_bn[OUTC+o+1], ti2 = g_bn[OUTC+o+2], ti3 = g_bn[OUTC+o+3];
    float sp0 = g_bn[2*OUTC+o], sp1 = g_bn[2*OUTC+o+1], sp2 = g_bn[2*OUTC+o+2], sp3 = g_bn[2*OUTC+o+3];
    float tp0 = g_bn[3*OUTC+o], tp1 = g_bn[3*OUTC+o+1], tp2 = g_bn[3*OUTC+o+2], tp3 = g_bn[3*OUTC+o+3];
    float4 r;
    r.x = fmaxf(yi0.x*si0 + ti0 + yp0.x*sp0 + tp0, 0.f);
    r.y = fmaxf(yi0.y*si1 + ti1 + yp0.y*sp1 + tp1, 0.f);
    r.z = fmaxf(yi1.x*si2 + ti2 + yp1.x*sp2 + tp2, 0.f);
    r.w = fmaxf(yi1.y*si3 + ti3 + yp1.y*sp3 + tp3, 0.f);
    ((float4*)out)[idx] = r;
}

// ---------------- launch ----------------
#define CONV_SMEM (1024 + 3*STAGE)   /* align slack + 3 stages = 99328 */

extern "C" void kernel_launch(void* const* d_in, const int* in_sizes, int n_in,
                              void* d_out, int out_size) {
    const float* img_feats = (const float*)d_in[0];
    const float* pts_xyz   = (const float*)d_in[1];
    const float* pts_feats = (const float*)d_in[2];
    const float* T         = (const float*)d_in[3];
    const float* Kmat      = (const float*)d_in[4];
    const float* conv_w    = (const float*)d_in[5];
    const float* conv_b    = (const float*)d_in[6];
    const float* img_w     = (const float*)d_in[7];
    // d_in[8] img_b: cancels exactly under batch-norm
    const float* img_gamma = (const float*)d_in[9];
    const float* img_beta  = (const float*)d_in[10];
    const float* pts_w     = (const float*)d_in[11];
    // d_in[12] pts_b: cancels exactly under batch-norm
    const float* pts_gamma = (const float*)d_in[13];
    const float* pts_beta  = (const float*)d_in[14];
    const int*   cam_ids   = (const int*)d_in[15];
    float* out = (float*)d_out;
    (void)in_sizes; (void)n_in; (void)out_size;

    cudaFuncSetAttribute(conv_mma_kernel, cudaFuncAttributeMaxDynamicSharedMemorySize, CONV_SMEM);

    transpose_kernel<<<dim3(NPIX/32, CIN/64, NLVL*NIMG), 256>>>(img_feats);
    fold_gemm_kernel<<<dim3(KDIM/128, NLVL), 256>>>(conv_w, img_w);
    c2_kernel<<<NLVL, 128>>>(img_w, conv_b);
    pts_fold_kernel<<<(PTSC*OUTC)/256, 256>>>(pts_w);
    conv_mma_kernel<<<dim3(NPIX/128, NIMG, NLVL), 256, CONV_SMEM>>>();
    sample_kernel<<<(TOTPTS/2*32)/256, 256>>>(pts_xyz, cam_ids, T, Kmat);
    ptsgemm_mma_kernel<<<TOTPTS/128, 256>>>(pts_feats);
    stats_kernel<<<TOTPTS/256, 128>>>();
    bnparams_kernel<<<1, 128>>>(img_gamma, img_beta, pts_gamma, pts_beta);
    finalize_kernel<<<(size_t)TOTPTS*OUTC/4/256, 256>>>(out);
}

// round 16
// speedup vs baseline: 1.2075x; 1.0478x over previous
#include <cuda_runtime.h>
#include <cuda_fp16.h>
#include <math.h>
#include <stdint.h>

#define NLVL 3
#define BATCH 2
#define NPTSB 65536
#define NCAMS 5
#define CIN 256
#define MID 128
#define OUTC 128
#define PTSC 128
#define HH 64
#define WW 112
#define NIMG (BATCH*NCAMS)          /* 10 */
#define NPIX (HH*WW)                /* 7168 */
#define KDIM (CIN*9)                /* 2304 */
#define TOTPTS (BATCH*NPTSB)        /* 131072 */
#define KCH 64                      /* K elements per pipeline chunk */
#define NCHUNK (KDIM/KCH)           /* 36 */
#define STAGE 32768                 /* A 16KB fp16 + B 16KB fp16 */
#define NCONVBLK (NPIX/128*NIMG*NLVL)   /* 1680 */
#define NPTSBLK (TOTPTS/128)            /* 1024 */

// ---------------- scratch (static device arrays) ----------------
__device__ float  g_c2[NLVL*OUTC];                             // folded conv bias [l][o]
__device__ __half g_w[(size_t)NLVL*NCHUNK*8192];               // folded conv weights fp16 (tap-major k), pre-swizzled 16KB tiles
__device__ __half g_pw[4*4096];                                // pts_w fp16, pre-swizzled 8KB chunk tiles
__device__ __half g_imgT[(size_t)NLVL*NIMG*NPIX*CIN];          // transposed+fp16 image [l][n][pix][ci]
__device__ __half g_conv[(size_t)NLVL*NIMG*NPIX*OUTC];         // projected conv features (fp16)
__device__ __half g_yimg[(size_t)TOTPTS*OUTC];                 // img branch pre-BN (fp16)
__device__ __half g_ypts[(size_t)TOTPTS*OUTC];                 // pts branch pre-BN (fp16)
__device__ double g_stats[4*OUTC];
__device__ float  g_bn[4*OUTC];

__constant__ int c_tapoff[9] = {-WW-1, -WW, -WW+1, -1, 0, 1, WW-1, WW, WW+1};

// ---------------- PTX helpers ----------------
__device__ __forceinline__ uint32_t smem_u32(const void* p) {
    uint32_t a;
    asm("{ .reg .u64 t; cvta.to.shared.u64 t, %1; cvt.u32.u64 %0, t; }" : "=r"(a) : "l"(p));
    return a;
}
#define LDSM4(r, addr) \
    asm volatile("ldmatrix.sync.aligned.m8n8.x4.shared.b16 {%0,%1,%2,%3}, [%4];" \
        : "=r"((r)[0]), "=r"((r)[1]), "=r"((r)[2]), "=r"((r)[3]) : "r"(addr))
#define MMAH16816(c, a, b0, b1) \
    asm volatile("mma.sync.aligned.m16n8k16.row.col.f32.f16.f16.f32 " \
        "{%0,%1,%2,%3}, {%4,%5,%6,%7}, {%8,%9}, {%0,%1,%2,%3};" \
        : "+f"((c)[0]), "+f"((c)[1]), "+f"((c)[2]), "+f"((c)[3]) \
        : "r"((a)[0]), "r"((a)[1]), "r"((a)[2]), "r"((a)[3]), "r"(b0), "r"(b1))
#define CP_ASYNC16(dst, src) \
    asm volatile("cp.async.cg.shared.global [%0], [%1], 16;" :: "r"(dst), "l"(src))
#define CP_ASYNC16Z(dst, src, sz) \
    asm volatile("cp.async.cg.shared.global [%0], [%1], 16, %2;" :: "r"(dst), "l"(src), "r"(sz))
#define CP_COMMIT() asm volatile("cp.async.commit_group;")
#define CP_WAIT0()  asm volatile("cp.async.wait_group 0;" ::: "memory")

// ---------------- transpose + fp16 convert: img[l][n][ci][pix] -> g_imgT[l][n][pix][ci] ----------------
__global__ __launch_bounds__(256) void transpose_kernel(const float* __restrict__ img) {
    __shared__ float t[64][33];
    const int zi = blockIdx.z;
    const int p0 = blockIdx.x * 32, c0 = blockIdx.y * 64;
    const float* src = img + (size_t)zi * CIN * NPIX;
    const int tx = threadIdx.x & 31, ty = threadIdx.x >> 5;   // ty 0..7
    #pragma unroll
    for (int j = 0; j < 8; j++)
        t[ty*8 + j][tx] = __ldg(&src[(size_t)(c0 + ty*8 + j) * NPIX + p0 + tx]);
    __syncthreads();
    __half* dst = g_imgT + (size_t)zi * NPIX * CIN;
    const int pp = threadIdx.x >> 3;        // 0..31 pixel
    const int cc = threadIdx.x & 7;         // 8-channel group
    uint32_t pk[4];
    #pragma unroll
    for (int q = 0; q < 4; q++) {
        __half2 h = __floats2half2_rn(t[cc*8 + 2*q][pp], t[cc*8 + 2*q + 1][pp]);
        pk[q] = *(uint32_t*)&h;
    }
    *(uint4*)&dst[(size_t)(p0 + pp) * CIN + c0 + cc*8] = make_uint4(pk[0], pk[1], pk[2], pk[3]);
}

// ---------------- fold as tiled GEMM: W2[l][o][k] = sum_m img_w[o][l*128+m] * conv_w[l][m][k] ----------------
__global__ __launch_bounds__(256) void fold_gemm_kernel(const float* __restrict__ conv_w,
                                                        const float* __restrict__ img_w) {
    __shared__ float As[8][128];   // [mm][o]
    __shared__ float Bs[8][132];   // [mm][k]
    const int l = blockIdx.y;
    const int kt = blockIdx.x * 128;
    const int tid = threadIdx.x;
    const int tm = tid >> 4, tn = tid & 15;

    float acc[8][8];
    #pragma unroll
    for (int i = 0; i < 8; i++)
        #pragma unroll
        for (int j = 0; j < 8; j++) acc[i][j] = 0.f;

    const float* cwb = conv_w + (size_t)l * MID * KDIM + kt;
    for (int m0 = 0; m0 < MID; m0 += 8) {
        #pragma unroll
        for (int q = 0; q < 4; q++) {
            int idx = tid * 4 + q;
            int mm = idx >> 7, o = idx & 127;
            As[mm][o] = __ldg(&img_w[(size_t)o * (MID*NLVL) + l*MID + m0 + mm]);
        }
        {
            int row = tid >> 5, col = (tid & 31) * 4;
            float4 v = __ldg((const float4*)&cwb[(size_t)(m0 + row) * KDIM + col]);
            Bs[row][col] = v.x; Bs[row][col+1] = v.y; Bs[row][col+2] = v.z; Bs[row][col+3] = v.w;
        }
        __syncthreads();
        #pragma unroll
        for (int mm = 0; mm < 8; mm++) {
            float a[8], b[8];
            #pragma unroll
            for (int i = 0; i < 8; i++) a[i] = As[mm][tm*8 + i];
            #pragma unroll
            for (int j = 0; j < 8; j++) b[j] = Bs[mm][tn*8 + j];
            #pragma unroll
            for (int i = 0; i < 8; i++)
                #pragma unroll
                for (int j = 0; j < 8; j++) acc[i][j] += a[i] * b[j];
        }
        __syncthreads();
    }
    #pragma unroll
    for (int i = 0; i < 8; i++) {
        int o = tm*8 + i;
        char* obase = (char*)g_w + (size_t)l * NCHUNK * 16384 + o*128;
        uint32_t sw = (uint32_t)((o & 7) << 4);
        #pragma unroll
        for (int j = 0; j < 8; j++) {
            int k = kt + tn*8 + j;
            int ci = k / 9, rs = k - ci * 9;
            int kn = rs * 256 + ci;
            int chunk = kn >> 6, kk = kn & 63;
            *(__half*)(obase + (size_t)chunk * 16384 + (((uint32_t)(kk*2)) ^ sw)) = __float2half(acc[i][j]);
        }
    }
}

// ---------------- c2 (folded conv bias) + stats zeroing ----------------
__global__ void c2_kernel(const float* __restrict__ img_w, const float* __restrict__ conv_b) {
    int l = blockIdx.x, o = threadIdx.x;
    if (l == 0) {
        #pragma unroll
        for (int j = 0; j < 4; j++) g_stats[j*128 + o] = 0.0;
    }
    const float* iw = img_w + (size_t)o*(MID*NLVL) + l*MID;
    float c = 0.f;
    for (int m = 0; m < MID; m++) c += iw[m] * conv_b[l*MID + m];
    g_c2[l*OUTC + o] = c;
}

// ---------------- pts_w -> fp16 pre-swizzled chunk tiles (8KB: row o = 64B, (o&3)<<4) ----------------
__global__ void pts_fold_kernel(const float* __restrict__ pts_w) {
    int idx = blockIdx.x * blockDim.x + threadIdx.x;   // 16384
    int o = idx >> 7, k = idx & 127;
    __half h = __float2half(__ldg(&pts_w[o*PTSC + k]));
    int chunk = k >> 5, kk = k & 31;
    *(__half*)((char*)g_pw + chunk*8192 + o*64 + (((kk*2)) ^ ((o & 3) << 4))) = h;
}

// ---------------- FUSED: conv (blocks [0,1680)) + pts GEMM (blocks [1680,2704)) ----------------
__global__ __launch_bounds__(256, 2) void convpts_kernel(const float* __restrict__ ptsA) {
    extern __shared__ char smem_raw[];
    uint32_t raw = smem_u32(smem_raw);
    uint32_t sb = (raw + 1023u) & ~1023u;
    const int bid = blockIdx.x;
    const int tid = threadIdx.x, wid = tid >> 5, lane = tid & 31;
    const int warp_m = wid >> 2, warp_n = wid & 3;

    if (bid < NCONVBLK) {
        // ================= conv path: 9 shifted GEMMs, fp16, fully-async, 3-stage =================
        const int l = bid / (NIMG * (NPIX/128));
        const int rem = bid - l * (NIMG * (NPIX/128));
        const int n = rem / (NPIX/128);
        const int m0 = (rem - n * (NPIX/128)) * 128;

        const __half* imgT = g_imgT + (size_t)(l*NIMG + n) * NPIX * CIN;
        const char* wb = (const char*)g_w + (size_t)l * NCHUNK * 16384;

        const int p_local = tid >> 1, hhalf = tid & 1;
        const int P = m0 + p_local;
        const int ypix = P / WW, xpix = P % WW;
        const uint32_t arow = (uint32_t)(p_local * 128);
        const uint32_t axor = (uint32_t)((p_local & 7) << 4);

        uint32_t vmask = 0;
        #pragma unroll
        for (int rs = 0; rs < 9; rs++) {
            int r = rs / 3 - 1, s = rs % 3 - 1;
            int ym = ypix + r, xm = xpix + s;
            if ((unsigned)ym < HH && (unsigned)xm < WW) vmask |= (1u << rs);
        }

        float acc[4][4][4];
        #pragma unroll
        for (int i = 0; i < 4; i++)
            #pragma unroll
            for (int j = 0; j < 4; j++)
                #pragma unroll
                for (int q = 0; q < 4; q++) acc[i][j][q] = 0.f;

        auto issue = [&](int c, int buf) {
            int rs = c >> 2, ci0 = (c & 3) << 6;
            int spix = P + c_tapoff[rs];
            spix = spix < 0 ? 0 : (spix > NPIX-1 ? NPIX-1 : spix);
            uint32_t sz = ((vmask >> rs) & 1) ? 16u : 0u;
            const char* asrc = (const char*)(imgT + (size_t)spix * CIN + ci0) + hhalf * 64;
            uint32_t adst = sb + (uint32_t)buf * STAGE + arow;
            #pragma unroll
            for (int q = 0; q < 4; q++) {
                uint32_t s16 = (uint32_t)(hhalf * 64 + q * 16);
                CP_ASYNC16Z(adst + (s16 ^ axor), asrc + q * 16, sz);
            }
            uint32_t bdst = sb + (uint32_t)buf * STAGE + 16384u;
            const char* bsrc = wb + (size_t)c * 16384;
            #pragma unroll
            for (int j = 0; j < 4; j++) {
                uint32_t off = (uint32_t)((j*256 + tid) * 16);
                CP_ASYNC16(bdst + off, bsrc + off);
            }
            CP_COMMIT();
        };

        const int ar0 = warp_m * 64 + (lane & 15);
        const int br0 = warp_n * 32 + (lane & 15);
        const uint32_t ax = (uint32_t)((ar0 & 7) << 4);
        const uint32_t kh = (uint32_t)((lane >> 4) << 4);
        auto compute = [&](int buf) {
            uint32_t st = sb + (uint32_t)buf * STAGE;
            uint32_t aB = st, bB = st + 16384u;
            #pragma unroll
            for (int s = 0; s < 4; s++) {
                uint32_t kb = (uint32_t)(s * 32) + kh;
                uint32_t bh[2][4];
                #pragma unroll
                for (int jb = 0; jb < 2; jb++) {
                    uint32_t row = (uint32_t)(br0 + jb*16);
                    LDSM4(bh[jb], bB + row*128 + (kb ^ ((row & 7) << 4)));
                }
                #pragma unroll
                for (int mi = 0; mi < 4; mi++) {
                    uint32_t ahr[4];
                    LDSM4(ahr, aB + (uint32_t)((ar0 + mi*16) * 128) + (kb ^ ax));
                    #pragma unroll
                    for (int ni = 0; ni < 4; ni++) {
                        int jb = ni >> 1, sel = ni & 1;
                        MMAH16816(acc[mi][ni], ahr, bh[jb][sel], bh[jb][sel+2]);
                    }
                }
            }
        };

        issue(0, 0);
        issue(1, 1);
        int buf = 0;
        for (int c = 0; c < NCHUNK; c++) {
            if (c + 1 < NCHUNK) { asm volatile("cp.async.wait_group 1;" ::: "memory"); }
            else                { asm volatile("cp.async.wait_group 0;" ::: "memory"); }
            __syncthreads();
            if (c + 2 < NCHUNK) {
                int nb = buf + 2; if (nb >= 3) nb -= 3;
                issue(c + 2, nb);
            }
            compute(buf);
            if (++buf == 3) buf = 0;
        }

        __half* ob = g_conv + ((size_t)(l*NIMG + n) * NPIX + m0) * OUTC;
        const int mrow = warp_m * 64 + (lane >> 2);
        const int ncol = warp_n * 32 + (lane & 3) * 2;
        #pragma unroll
        for (int mi = 0; mi < 4; mi++) {
            #pragma unroll
            for (int ni = 0; ni < 4; ni++) {
                int m = mrow + mi*16;
                int o = ncol + ni*8;
                *(__half2*)&ob[(size_t)m*OUTC + o]     = __floats2half2_rn(acc[mi][ni][0], acc[mi][ni][1]);
                *(__half2*)&ob[(size_t)(m+8)*OUTC + o] = __floats2half2_rn(acc[mi][ni][2], acc[mi][ni][3]);
            }
        }
    } else {
        // ================= pts GEMM path (fp16 2-pass): [131072,128] x [128,128] =================
        const int m0 = (bid - NCONVBLK) * 128;
        char* psm = smem_raw + (sb - raw);

        const int p_local = tid >> 1, hhalf = tid & 1;
        const uint32_t arow = (uint32_t)(p_local * 128);
        const uint32_t axor = (uint32_t)((p_local & 7) << 4);
        const float* ag = ptsA + (size_t)(m0 + p_local) * PTSC;

        float acc[4][4][4];
        #pragma unroll
        for (int i = 0; i < 4; i++)
            #pragma unroll
            for (int j = 0; j < 4; j++)
                #pragma unroll
                for (int q = 0; q < 4; q++) acc[i][j][q] = 0.f;

        const int ar0 = warp_m * 64 + (lane & 15);
        const int br0 = warp_n * 32 + (lane & 15);
        const uint32_t ax = (uint32_t)((ar0 & 7) << 4);
        const uint32_t kh = (uint32_t)((lane >> 4) << 4);

        for (int c = 0; c < 4; c++) {
            #pragma unroll
            for (int j = 0; j < 2; j++) {
                uint32_t off = (uint32_t)((j*256 + tid) * 16);
                CP_ASYNC16(sb + 16384u + off, (const char*)g_pw + c*8192 + off);
            }
            CP_COMMIT();
            const float* src = ag + c*32 + hhalf*16;
            #pragma unroll
            for (int j = 0; j < 8; j++) {
                float v0 = src[2*j], v1 = src[2*j+1];
                __half h0 = __float2half(v0), h1 = __float2half(v1);
                float l0 = v0 - __half2float(h0);
                float l1 = v1 - __half2float(h1);
                uint32_t hpair = (uint32_t)__half_as_ushort(h0) | ((uint32_t)__half_as_ushort(h1) << 16);
                uint32_t lpair;
                asm("cvt.rn.f16x2.f32 %0, %1, %2;" : "=r"(lpair) : "f"(l1), "f"(l0));
                uint32_t colb = (uint32_t)(hhalf * 32 + 4*j);
                *(uint32_t*)(psm + arow + (colb ^ axor))        = hpair;
                *(uint32_t*)(psm + arow + ((64 + colb) ^ axor)) = lpair;
            }
            CP_WAIT0();
            __syncthreads();
            #pragma unroll
            for (int s = 0; s < 2; s++) {
                uint32_t kb = (uint32_t)(s * 32) + kh;
                uint32_t bh[2][4];
                #pragma unroll
                for (int jb = 0; jb < 2; jb++) {
                    uint32_t row = (uint32_t)(br0 + jb*16);
                    LDSM4(bh[jb], sb + 16384u + row*64 + (kb ^ ((row & 3) << 4)));
                }
                #pragma unroll
                for (int mi = 0; mi < 4; mi++) {
                    uint32_t aoff = (uint32_t)((ar0 + mi*16) * 128);
                    uint32_t ahr[4], alr[4];
                    LDSM4(ahr, sb + aoff + (kb ^ ax));
                    LDSM4(alr, sb + aoff + ((64 + kb) ^ ax));
                    #pragma unroll
                    for (int ni = 0; ni < 4; ni++) {
                        int jb = ni >> 1, sel = ni & 1;
                        MMAH16816(acc[mi][ni], ahr, bh[jb][sel], bh[jb][sel+2]);
                        MMAH16816(acc[mi][ni], alr, bh[jb][sel], bh[jb][sel+2]);
                    }
                }
            }
            __syncthreads();
        }

        __half* ob = g_ypts + (size_t)m0 * OUTC;
        const int mrow = warp_m * 64 + (lane >> 2);
        const int ncol = warp_n * 32 + (lane & 3) * 2;
        #pragma unroll
        for (int mi = 0; mi < 4; mi++) {
            #pragma unroll
            for (int ni = 0; ni < 4; ni++) {
                int m = mrow + mi*16;
                int o = ncol + ni*8;
                *(__half2*)&ob[(size_t)m*OUTC + o]     = __floats2half2_rn(acc[mi][ni][0], acc[mi][ni][1]);
                *(__half2*)&ob[(size_t)(m+8)*OUTC + o] = __floats2half2_rn(acc[mi][ni][2], acc[mi][ni][3]);
            }
        }
    }
}

// ---------------- projection + bilinear gather (HALF-warp per point, uint4 lanes) ----------------
__global__ __launch_bounds__(256) void sample_kernel(const float* __restrict__ pts_xyz,
                                                     const int* __restrict__ cam_ids,
                                                     const float* __restrict__ T,
                                                     const float* __restrict__ Kmat) {
    int w = (blockIdx.x * blockDim.x + threadIdx.x) >> 5;      // warp id
    int lane = threadIdx.x & 31;
    int half = lane >> 4;                                      // which point in the warp
    int lane16 = lane & 15;                                    // 16B-chunk index (8 channels)
    int p = w * 2 + half;
    if (p >= TOTPTS) return;
    int b = p >> 16;
    int cam = __ldg(&cam_ids[p]);
    float x = __ldg(&pts_xyz[p*3+0]);
    float y = __ldg(&pts_xyz[p*3+1]);
    float z = __ldg(&pts_xyz[p*3+2]);
    const float* t = T + cam*16;
    float pcx = t[0]*x + t[1]*y + t[2]*z  + t[3];
    float pcy = t[4]*x + t[5]*y + t[6]*z  + t[7];
    float pcz = t[8]*x + t[9]*y + t[10]*z + t[11];
    const float* km = Kmat + cam*9;
    float pim0 = (km[0]*0.125f)*pcx + km[1]*pcy + (km[2]*0.125f)*pcz;
    float pim1 = km[3]*pcx + (km[4]*0.125f)*pcy + (km[5]*0.125f)*pcz;
    float pim2 = km[6]*pcx + km[7]*pcy + km[8]*pcz;
    float u = pim0 / pim2, v = pim1 / pim2;
    float px = u * ((float)(WW-1)/(float)WW);
    float py = v * ((float)(HH-1)/(float)HH);
    float x0 = floorf(px), y0 = floorf(py);
    float wx1 = px - x0, wy1 = py - y0;
    float wx0 = 1.f - wx1, wy0 = 1.f - wy1;

    float xs[2] = {x0, x0 + 1.f};
    float ys[2] = {y0, y0 + 1.f};
    float wxs[2] = {wx0, wx1};
    float wys[2] = {wy0, wy1};
    float cw[4];
    int   cox[4], coy[4];
    float wsum = 0.f;
    #pragma unroll
    for (int cy = 0; cy < 2; cy++)
        #pragma unroll
        for (int cx = 0; cx < 2; cx++) {
            float xf = xs[cx], yf = ys[cy];
            bool valid = (xf >= 0.f) & (xf <= (float)(WW-1)) & (yf >= 0.f) & (yf <= (float)(HH-1));
            float wgt = valid ? (wxs[cx] * wys[cy]) : 0.f;
            cw[cy*2+cx] = wgt;
            wsum += wgt;
            cox[cy*2+cx] = (int)fminf(fmaxf(xf, 0.f), (float)(WW-1));
            coy[cy*2+cx] = (int)fminf(fmaxf(yf, 0.f), (float)(HH-1));
        }

    int img = b * NCAMS + cam;
    float af[8];
    #pragma unroll
    for (int q = 0; q < 8; q++) af[q] = 0.f;
    #pragma unroll
    for (int l = 0; l < NLVL; l++) {
        const __half* basep = g_conv + (size_t)(l*NIMG + img) * NPIX * OUTC;
        #pragma unroll
        for (int c = 0; c < 4; c++) {
            float wgt = cw[c];
            if (wgt != 0.f) {
                const uint4* src = (const uint4*)(basep + ((size_t)coy[c]*WW + cox[c]) * OUTC) + lane16;
                uint4 d = __ldg(src);
                float2 f0 = __half22float2(*(__half2*)&d.x);
                float2 f1 = __half22float2(*(__half2*)&d.y);
                float2 f2 = __half22float2(*(__half2*)&d.z);
                float2 f3 = __half22float2(*(__half2*)&d.w);
                af[0] += wgt * f0.x; af[1] += wgt * f0.y;
                af[2] += wgt * f1.x; af[3] += wgt * f1.y;
                af[4] += wgt * f2.x; af[5] += wgt * f2.y;
                af[6] += wgt * f3.x; af[7] += wgt * f3.y;
            }
        }
        const float4* c2p = (const float4*)(g_c2 + l*OUTC) + lane16*2;
        float4 ca = __ldg(c2p);
        float4 cb = __ldg(c2p + 1);
        af[0] += wsum * ca.x; af[1] += wsum * ca.y; af[2] += wsum * ca.z; af[3] += wsum * ca.w;
        af[4] += wsum * cb.x; af[5] += wsum * cb.y; af[6] += wsum * cb.z; af[7] += wsum * cb.w;
    }
    __half2 h0 = __floats2half2_rn(af[0], af[1]);
    __half2 h1 = __floats2half2_rn(af[2], af[3]);
    __half2 h2 = __floats2half2_rn(af[4], af[5]);
    __half2 h3 = __floats2half2_rn(af[6], af[7]);
    ((uint4*)(g_yimg + (size_t)p * OUTC))[lane16] =
        make_uint4(*(uint32_t*)&h0, *(uint32_t*)&h1, *(uint32_t*)&h2, *(uint32_t*)&h3);
}

// ---------------- BN statistics (both branches, fp16 inputs) ----------------
__global__ void stats_kernel() {
    int o = threadIdx.x;                 // 0..127
    size_t r0 = (size_t)blockIdx.x * 256;
    float si = 0.f, qi = 0.f, sp = 0.f, qp = 0.f;
    for (int r = 0; r < 256; r++) {
        float vi = __half2float(g_yimg[(r0 + r) * OUTC + o]);
        float vp = __half2float(g_ypts[(r0 + r) * OUTC + o]);
        si += vi; qi += vi * vi;
        sp += vp; qp += vp * vp;
    }
    atomicAdd(&g_stats[o],          (double)si);
    atomicAdd(&g_stats[OUTC + o],   (double)qi);
    atomicAdd(&g_stats[2*OUTC + o], (double)sp);
    atomicAdd(&g_stats[3*OUTC + o], (double)qp);
}

__global__ void bnparams_kernel(const float* __restrict__ gi, const float* __restrict__ bi,
                                const float* __restrict__ gp, const float* __restrict__ bp) {
    int o = threadIdx.x;
    double n = (double)TOTPTS;
    double mi = g_stats[o] / n;
    double vi = g_stats[OUTC + o] / n - mi * mi;
    float s = gi[o] / sqrtf((float)vi + 1e-3f);
    g_bn[o] = s;
    g_bn[OUTC + o] = bi[o] - (float)mi * s;
    double mp = g_stats[2*OUTC + o] / n;
    double vp = g_stats[3*OUTC + o] / n - mp * mp;
    float s2 = gp[o] / sqrtf((float)vp + 1e-3f);
    g_bn[2*OUTC + o] = s2;
    g_bn[3*OUTC + o] = bp[o] - (float)mp * s2;
}

// ---------------- finalize: relu(BN(img) + BN(pts)) (fp16 inputs, fp32 output) ----------------
__global__ __launch_bounds__(256) void finalize_kernel(float* __restrict__ out) {
    size_t idx = (size_t)blockIdx.x * blockDim.x + threadIdx.x;   // 4-element group index
    int o = (int)(idx & 31) * 4;
    uint2 di = ((const uint2*)g_yimg)[idx];
    uint2 dp = ((const uint2*)g_ypts)[idx];
    float2 yi0 = __half22float2(*(__half2*)&di.x);
    float2 yi1 = __half22float2(*(__half2*)&di.y);
    float2 yp0 = __half22float2(*(__half2*)&dp.x);
    float2 yp1 = __half22float2(*(__half2*)&dp.y);
    float si0 = g_bn[o], si1 = g_bn[o+1], si2 = g_bn[o+2], si3 = g_bn[o+3];
    float ti0 = g_bn[OUTC+o], ti1 = g_bn[OUTC+o+1], ti2 = g_bn[OUTC+o+2], ti3 = g_bn[OUTC+o+3];
    float sp0 = g_bn[2*OUTC+o], sp1 = g_bn[2*OUTC+o+1], sp2 = g_bn[2*OUTC+o+2], sp3 = g_bn[2*OUTC+o+3];
    float tp0 = g_bn[3*OUTC+o], tp1 = g_bn[3*OUTC+o+1], tp2 = g_bn[3*OUTC+o+2], tp3 = g_bn[3*OUTC+o+3];
    float4 r;
    r.x = fmaxf(yi0.x*si0 + ti0 + yp0.x*sp0 + tp0, 0.f);
    r.y = fmaxf(yi0.y*si1 + ti1 + yp0.y*sp1 + tp1, 0.f);
    r.z = fmaxf(yi1.x*si2 + ti2 + yp1.x*sp2 + tp2, 0.f);
    r.w = fmaxf(yi1.y*si3 + ti3 + yp1.y*sp3 + tp3, 0.f);
    ((float4*)out)[idx] = r;
}

// ---------------- launch ----------------
#define CONV_SMEM (1024 + 3*STAGE)   /* align slack + 3 stages = 99328 */

extern "C" void kernel_launch(void* const* d_in, const int* in_sizes, int n_in,
                              void* d_out, int out_size) {
    const float* img_feats = (const float*)d_in[0];
    const float* pts_xyz   = (const float*)d_in[1];
    const float* pts_feats = (const float*)d_in[2];
    const float* T         = (const float*)d_in[3];
    const float* Kmat      = (const float*)d_in[4];
    const float* conv_w    = (const float*)d_in[5];
    const float* conv_b    = (const float*)d_in[6];
    const float* img_w     = (const float*)d_in[7];
    // d_in[8] img_b: cancels exactly under batch-norm
    const float* img_gamma = (const float*)d_in[9];
    const float* img_beta  = (const float*)d_in[10];
    const float* pts_w     = (const float*)d_in[11];
    // d_in[12] pts_b: cancels exactly under batch-norm
    const float* pts_gamma = (const float*)d_in[13];
    const float* pts_beta  = (const float*)d_in[14];
    const int*   cam_ids   = (const int*)d_in[15];
    float* out = (float*)d_out;
    (void)in_sizes; (void)n_in; (void)out_size;

    cudaFuncSetAttribute(convpts_kernel, cudaFuncAttributeMaxDynamicSharedMemorySize, CONV_SMEM);

    transpose_kernel<<<dim3(NPIX/32, CIN/64, NLVL*NIMG), 256>>>(img_feats);
    fold_gemm_kernel<<<dim3(KDIM/128, NLVL), 256>>>(conv_w, img_w);
    c2_kernel<<<NLVL, 128>>>(img_w, conv_b);
    pts_fold_kernel<<<(PTSC*OUTC)/256, 256>>>(pts_w);
    convpts_kernel<<<NCONVBLK + NPTSBLK, 256, CONV_SMEM>>>(pts_feats);
    sample_kernel<<<(TOTPTS/2*32)/256, 256>>>(pts_xyz, cam_ids, T, Kmat);
    stats_kernel<<<TOTPTS/256, 128>>>();
    bnparams_kernel<<<1, 128>>>(img_gamma, img_beta, pts_gamma, pts_beta);
    finalize_kernel<<<(size_t)TOTPTS*OUTC/4/256, 256>>>(out);
}